// round 11
// baseline (speedup 1.0000x reference)
#include <cuda_runtime.h>
#include <cuda_fp16.h>
#include <math.h>

#define NN   50000
#define EE   800000
#define IND  128
#define OUTD 128
#define HH   4
#define CC   32
#define PP   3
#define TOT  384
#define NEGS 0.2f
#define LN_EPS 1e-5f

// ---------------- scratch (static device globals; no allocation) ------------
__device__ __half g_XLh[PP * NN * OUTD];   // fp16 x@Wl+bl per path
__device__ __half g_XRh[PP * NN * OUTD];   // fp16 x@Wr+br per path
__device__ __half g_xh[NN * IND];          // fp16 copy of x
__device__ __half g_Wlh[PP * IND * OUTD];  // fp16 Wl
__device__ __half g_Wrh[PP * IND * OUTD];  // fp16 Wr
__device__ float  g_ALs[PP * NN * HH];     // att-dot of xl per node/head
__device__ int    g_deg[NN];
__device__ int    g_off[NN];
__device__ int    g_wp[NN];
__device__ int    g_srcv[EE];
__device__ int    g_dstv[EE];
__device__ int    g_csr[EE];
__device__ int    g_bsum[64];
__device__ int    g_is64;

// 8-lane head-group sum (butterfly; redux.f32 does not exist on sm_100)
__device__ __forceinline__ float group8_sum(float v) {
    v += __shfl_xor_sync(0xffffffffu, v, 1);
    v += __shfl_xor_sync(0xffffffffu, v, 2);
    v += __shfl_xor_sync(0xffffffffu, v, 4);
    return v;
}

// ---------------- init: zero degrees + dtype probe (block 0) ----------------
__global__ void k_init(const unsigned int* __restrict__ ei32) {
    int i = blockIdx.x * blockDim.x + threadIdx.x;
    if (i < NN) g_deg[i] = 0;
    if (blockIdx.x == 0) {
        __shared__ int bad;
        if (threadIdx.x == 0) bad = 0;
        __syncthreads();
        int local = 0;
        for (int j = threadIdx.x; j < 4096; j += blockDim.x) {
            if (ei32[2 * j + 1] != 0u) local = 1;
        }
        if (local) atomicAdd(&bad, 1);
        __syncthreads();
        if (threadIdx.x == 0) g_is64 = (bad == 0) ? 1 : 0;
    }
}

__global__ void k_convert_count(const void* __restrict__ ei) {
    int e = blockIdx.x * blockDim.x + threadIdx.x;
    if (e >= EE) return;
    int src, dst;
    if (g_is64) {
        const long long* p = (const long long*)ei;
        src = (int)p[e];
        dst = (int)p[EE + e];
    } else {
        const int* p = (const int*)ei;
        src = p[e];
        dst = p[EE + e];
    }
    g_srcv[e] = src;
    g_dstv[e] = dst;
    atomicAdd(&g_deg[dst], 1);
}

// ---------------- pre-convert x / Wl / Wr to fp16 ---------------------------
__device__ __forceinline__ uint4 pack8h(float4 v0, float4 v1) {
    __half2 h0 = __floats2half2_rn(v0.x, v0.y);
    __half2 h1 = __floats2half2_rn(v0.z, v0.w);
    __half2 h2 = __floats2half2_rn(v1.x, v1.y);
    __half2 h3 = __floats2half2_rn(v1.z, v1.w);
    uint4 u;
    u.x = *(unsigned*)&h0; u.y = *(unsigned*)&h1;
    u.z = *(unsigned*)&h2; u.w = *(unsigned*)&h3;
    return u;
}

#define XCHUNKS (NN * IND / 8)            // 800000
#define WCHUNKS (PP * IND * OUTD / 8)     // 6144

__global__ void k_xwconv(const float* __restrict__ x,
                         const float* __restrict__ Wl,
                         const float* __restrict__ Wr) {
    int t = blockIdx.x * blockDim.x + threadIdx.x;
    if (t < XCHUNKS) {
        const float* sp = x + (size_t)t * 8;
        *(uint4*)&g_xh[(size_t)t * 8] =
            pack8h(*(const float4*)sp, *(const float4*)(sp + 4));
    } else if (t < XCHUNKS + WCHUNKS) {
        int i = t - XCHUNKS;
        const float* sp = Wl + (size_t)i * 8;
        *(uint4*)&g_Wlh[(size_t)i * 8] =
            pack8h(*(const float4*)sp, *(const float4*)(sp + 4));
    } else if (t < XCHUNKS + 2 * WCHUNKS) {
        int i = t - XCHUNKS - WCHUNKS;
        const float* sp = Wr + (size_t)i * 8;
        *(uint4*)&g_Wrh[(size_t)i * 8] =
            pack8h(*(const float4*)sp, *(const float4*)(sp + 4));
    }
}

// ---------------- exclusive scan over degrees -------------------------------
#define SCAN_T 1024
#define SCAN_NB ((NN + SCAN_T - 1) / SCAN_T)   // 49

__global__ void k_scan1() {
    __shared__ int sh[SCAN_T];
    int i = blockIdx.x * SCAN_T + threadIdx.x;
    int v = (i < NN) ? g_deg[i] : 0;
    sh[threadIdx.x] = v;
    __syncthreads();
    for (int d = 1; d < SCAN_T; d <<= 1) {
        int t = (threadIdx.x >= d) ? sh[threadIdx.x - d] : 0;
        __syncthreads();
        sh[threadIdx.x] += t;
        __syncthreads();
    }
    int incl = sh[threadIdx.x];
    if (i < NN) g_off[i] = incl - v;
    if (threadIdx.x == SCAN_T - 1) g_bsum[blockIdx.x] = incl;
}

__global__ void k_scan23() {
    __shared__ int pre;
    if (threadIdx.x == 0) {
        int r = 0;
        for (int b = 0; b < (int)blockIdx.x; b++) r += g_bsum[b];
        pre = r;
    }
    __syncthreads();
    int i = blockIdx.x * SCAN_T + threadIdx.x;
    if (i < NN) {
        int o = g_off[i] + pre;
        g_off[i] = o;
        g_wp[i]  = o;
    }
}

__global__ void k_scatter() {
    int e = blockIdx.x * blockDim.x + threadIdx.x;
    if (e >= EE) return;
    int pos = atomicAdd(&g_wp[g_dstv[e]], 1);
    g_csr[pos] = g_srcv[e];
}

// ---------------- fp16 tensor-core GEMM (m16n8k16 + ldmatrix) ---------------
// grid (391, 3). Whole-K fp16 tiles in smem; phases l/r. AL computed in
// phase-0 epilogue from register-resident accumulators (heads align to warps).
#define ST 136
#define A_OFF  0
#define BL_OFF (128 * ST)
#define BR_OFF (256 * ST)
#define GEMM_SMEM (384 * ST * 2)    // 104448 bytes

__global__ void __launch_bounds__(256) k_gemm(
    const float* __restrict__ bl, const float* __restrict__ br,
    const float* __restrict__ att) {
    extern __shared__ __half sm[];
    const int p    = blockIdx.y;
    const int tid  = threadIdx.x;
    const int wid  = tid >> 5;
    const int lane = tid & 31;
    const int wm   = wid & 3;
    const int wn   = wid >> 2;
    const int grp  = lane >> 2;
    const int tig  = lane & 3;
    const int sel  = lane >> 3;
    const int rin  = lane & 7;
    const int row0 = blockIdx.x * 128;

    for (int i = tid; i < 128 * 16; i += 256) {
        int r = i >> 4, seg = i & 15;
        uint4 v = make_uint4(0u, 0u, 0u, 0u);
        if (row0 + r < NN)
            v = *(const uint4*)&g_xh[(size_t)(row0 + r) * IND + seg * 8];
        *(uint4*)&sm[A_OFF + r * ST + seg * 8] = v;
    }
    for (int i = tid; i < 128 * 16; i += 256) {
        int k = i >> 4, seg = i & 15;
        *(uint4*)&sm[BL_OFF + k * ST + seg * 8] =
            *(const uint4*)&g_Wlh[((size_t)p * IND + k) * OUTD + seg * 8];
        *(uint4*)&sm[BR_OFF + k * ST + seg * 8] =
            *(const uint4*)&g_Wrh[((size_t)p * IND + k) * OUTD + seg * 8];
    }
    __syncthreads();

    const unsigned smem_u32 = (unsigned)__cvta_generic_to_shared(sm);

#pragma unroll
    for (int phase = 0; phase < 2; phase++) {
        const int boff = phase ? BR_OFF : BL_OFF;
        const float* bias = phase ? (br + p * OUTD) : (bl + p * OUTD);
        __half* out = phase ? (g_XRh + (size_t)p * NN * OUTD)
                            : (g_XLh + (size_t)p * NN * OUTD);

        float c[2][8][4];
#pragma unroll
        for (int mt = 0; mt < 2; mt++)
#pragma unroll
            for (int nt = 0; nt < 8; nt++)
#pragma unroll
                for (int j = 0; j < 4; j++) c[mt][nt][j] = 0.f;

#pragma unroll
        for (int ks = 0; ks < 8; ks++) {
            unsigned a[2][4];
#pragma unroll
            for (int mt = 0; mt < 2; mt++) {
                int arow = wm * 32 + mt * 16 + (sel & 1) * 8 + rin;
                int koff = ks * 16 + (sel >> 1) * 8;
                unsigned addr = smem_u32 + (unsigned)(A_OFF + arow * ST + koff) * 2u;
                asm volatile(
                    "ldmatrix.sync.aligned.m8n8.x4.shared.b16 {%0,%1,%2,%3}, [%4];"
                    : "=r"(a[mt][0]), "=r"(a[mt][1]), "=r"(a[mt][2]), "=r"(a[mt][3])
                    : "r"(addr));
            }
            unsigned b[4][4];
#pragma unroll
            for (int ntp = 0; ntp < 4; ntp++) {
                int n0   = wn * 64 + ntp * 16 + (sel >> 1) * 8;
                int krow = ks * 16 + (sel & 1) * 8 + rin;
                unsigned addr = smem_u32 + (unsigned)(boff + krow * ST + n0) * 2u;
                asm volatile(
                    "ldmatrix.sync.aligned.m8n8.x4.trans.shared.b16 {%0,%1,%2,%3}, [%4];"
                    : "=r"(b[ntp][0]), "=r"(b[ntp][1]), "=r"(b[ntp][2]), "=r"(b[ntp][3])
                    : "r"(addr));
            }
#pragma unroll
            for (int ntp = 0; ntp < 4; ntp++) {
#pragma unroll
                for (int half_n = 0; half_n < 2; half_n++) {
                    int nt = ntp * 2 + half_n;
                    unsigned b0 = b[ntp][half_n * 2];
                    unsigned b1 = b[ntp][half_n * 2 + 1];
#pragma unroll
                    for (int mt = 0; mt < 2; mt++) {
                        asm volatile(
                            "mma.sync.aligned.m16n8k16.row.col.f32.f16.f16.f32 "
                            "{%0,%1,%2,%3}, {%4,%5,%6,%7}, {%8,%9}, {%0,%1,%2,%3};"
                            : "+f"(c[mt][nt][0]), "+f"(c[mt][nt][1]),
                              "+f"(c[mt][nt][2]), "+f"(c[mt][nt][3])
                            : "r"(a[mt][0]), "r"(a[mt][1]),
                              "r"(a[mt][2]), "r"(a[mt][3]),
                              "r"(b0), "r"(b1));
                    }
                }
            }
        }

        // epilogue: +bias, fp16 store; phase 0 also reduces AL in-warp.
        float alp[4][2];
#pragma unroll
        for (int ri = 0; ri < 4; ri++) { alp[ri][0] = 0.f; alp[ri][1] = 0.f; }

#pragma unroll
        for (int mt = 0; mt < 2; mt++) {
#pragma unroll
            for (int nt = 0; nt < 8; nt++) {
                int col = wn * 64 + nt * 8 + 2 * tig;
                float b0 = bias[col], b1 = bias[col + 1];
                float v0 = c[mt][nt][0] + b0, v1 = c[mt][nt][1] + b1;
                float v2 = c[mt][nt][2] + b0, v3 = c[mt][nt][3] + b1;
                int r0 = row0 + wm * 32 + mt * 16 + grp;
                if (r0 < NN)
                    *(__half2*)(out + (size_t)r0 * OUTD + col) =
                        __floats2half2_rn(v0, v1);
                if (r0 + 8 < NN)
                    *(__half2*)(out + (size_t)(r0 + 8) * OUTD + col) =
                        __floats2half2_rn(v2, v3);
                if (phase == 0) {
                    float a0 = att[p * (HH * CC) + col];
                    float a1 = att[p * (HH * CC) + col + 1];
                    int h = nt >> 2;
                    alp[mt * 2 + 0][h] += a0 * v0 + a1 * v1;
                    alp[mt * 2 + 1][h] += a0 * v2 + a1 * v3;
                }
            }
        }
        if (phase == 0) {
#pragma unroll
            for (int ri = 0; ri < 4; ri++)
#pragma unroll
                for (int h = 0; h < 2; h++) {
                    alp[ri][h] += __shfl_xor_sync(0xffffffffu, alp[ri][h], 1);
                    alp[ri][h] += __shfl_xor_sync(0xffffffffu, alp[ri][h], 2);
                }
            if (tig == 0) {
#pragma unroll
                for (int ri = 0; ri < 4; ri++) {
                    int row = row0 + wm * 32 + (ri >> 1) * 16 + grp + (ri & 1) * 8;
                    if (row < NN) {
                        g_ALs[((size_t)p * NN + row) * HH + 2 * wn + 0] = alp[ri][0];
                        g_ALs[((size_t)p * NN + row) * HH + 2 * wn + 1] = alp[ri][1];
                    }
                }
            }
        }
    }
}

// ---------------- helpers ---------------------------------------------------
__device__ __forceinline__ float4 loadh4(const __half* base) {
    uint2 u = *(const uint2*)base;
    __half2 h0 = *(__half2*)&u.x;
    __half2 h1 = *(__half2*)&u.y;
    float2 f0 = __half22float2(h0);
    float2 f1 = __half22float2(h1);
    return make_float4(f0.x, f0.y, f1.x, f1.y);
}

// ---------------- fused node kernel: GATv2 + LayerNorm, 3 sequential passes -
// Per-pass state is ONE path (q, a4, acc, s, base) -> ~55 regs -> 32 warps/SM.
// score = 0.6*(AL[src]+AR[n]) + 0.4*sum_c att*|xl+xr|   (exact factorization)
__global__ void __launch_bounds__(256, 4) k_node_ln(
    const float* __restrict__ att, const float* __restrict__ out_bias,
    const float* __restrict__ gamma, const float* __restrict__ beta,
    float* __restrict__ out) {
    int warp = (blockIdx.x * blockDim.x + threadIdx.x) >> 5;
    int lane = threadIdx.x & 31;
    if (warp >= NN) return;
    const int n = warp;
    const int hh = lane >> 3;

    const int off = g_off[n];
    const int deg = g_deg[n];

    float4 o[PP];

#pragma unroll
    for (int p = 0; p < PP; p++) {
        const __half* XLb = g_XLh + (size_t)p * NN * OUTD + lane * 4;
        const float*  ALb = g_ALs + (size_t)p * NN * HH + hh;
        float4 q  = loadh4(g_XRh + ((size_t)p * NN + n) * OUTD + lane * 4);
        float4 a4 = *(const float4*)(att + p * (HH * CC) + lane * 4);

        float t0 = a4.x * q.x + a4.y * q.y + a4.z * q.z + a4.w * q.w;
        float base = 0.6f * group8_sum(t0);

        float s = 0.f;
        float4 acc = make_float4(0.f, 0.f, 0.f, 0.f);

        // self loop + edges; e==-1 is the self loop
        int nx = (deg > 0) ? g_csr[off] : 0;
        for (int e = -1; e < deg; e++) {
            int src;
            if (e < 0) {
                src = n;
            } else {
                src = nx;
                if (e + 1 < deg) nx = g_csr[off + e + 1];
            }
            float4 xl = loadh4(XLb + (size_t)src * OUTD);
            float  al = ALb[(size_t)src * HH];
            float mx = xl.x + q.x, my = xl.y + q.y;
            float mz = xl.z + q.z, mw = xl.w + q.w;
            float t = a4.x * fabsf(mx) + a4.y * fabsf(my)
                    + a4.z * fabsf(mz) + a4.w * fabsf(mw);
            t = group8_sum(t);
            float score = fmaf(0.4f, t, fmaf(0.6f, al, base));
            float pe = __expf(score);
            s += pe;
            acc.x = fmaf(pe, xl.x, acc.x);
            acc.y = fmaf(pe, xl.y, acc.y);
            acc.z = fmaf(pe, xl.z, acc.z);
            acc.w = fmaf(pe, xl.w, acc.w);
        }

        float inv = 1.f / s;
        const float* ob = out_bias + p * OUTD + lane * 4;
        o[p].x = fmaxf(0.f, acc.x * inv + ob[0]);
        o[p].y = fmaxf(0.f, acc.y * inv + ob[1]);
        o[p].z = fmaxf(0.f, acc.z * inv + ob[2]);
        o[p].w = fmaxf(0.f, acc.w * inv + ob[3]);
    }

    // LayerNorm across 384 channels held by this warp
    float sum = 0.f;
#pragma unroll
    for (int p = 0; p < PP; p++)
        sum += o[p].x + o[p].y + o[p].z + o[p].w;
#pragma unroll
    for (int d = 16; d >= 1; d >>= 1) sum += __shfl_xor_sync(0xffffffffu, sum, d);
    float mu = sum * (1.f / TOT);

    float vs = 0.f;
#pragma unroll
    for (int p = 0; p < PP; p++) {
        float dx = o[p].x - mu, dy = o[p].y - mu;
        float dz = o[p].z - mu, dw = o[p].w - mu;
        vs += dx * dx + dy * dy + dz * dz + dw * dw;
    }
#pragma unroll
    for (int d = 16; d >= 1; d >>= 1) vs += __shfl_xor_sync(0xffffffffu, vs, d);
    float r = rsqrtf(vs * (1.f / TOT) + LN_EPS);

#pragma unroll
    for (int p = 0; p < PP; p++) {
        int idx = p * OUTD + lane * 4;
        float4 g = *(const float4*)(gamma + idx);
        float4 b = *(const float4*)(beta + idx);
        float4 w;
        w.x = (o[p].x - mu) * r * g.x + b.x;
        w.y = (o[p].y - mu) * r * g.y + b.y;
        w.z = (o[p].z - mu) * r * g.z + b.z;
        w.w = (o[p].w - mu) * r * g.w + b.w;
        *(float4*)(out + (size_t)n * TOT + idx) = w;
    }
}

// ---------------- launch ----------------------------------------------------
extern "C" void kernel_launch(void* const* d_in, const int* in_sizes, int n_in,
                              void* d_out, int out_size) {
    const float* x        = (const float*)d_in[0];
    const void*  ei       = d_in[1];
    const float* Wl       = (const float*)d_in[2];
    const float* bl       = (const float*)d_in[3];
    const float* Wr       = (const float*)d_in[4];
    const float* br       = (const float*)d_in[5];
    const float* att      = (const float*)d_in[6];
    const float* out_bias = (const float*)d_in[7];
    const float* gamma    = (const float*)d_in[8];
    const float* beta     = (const float*)d_in[9];
    float* out = (float*)d_out;

    const int TB = 256;

    cudaFuncSetAttribute(k_gemm, cudaFuncAttributeMaxDynamicSharedMemorySize,
                         GEMM_SMEM);

    k_init<<<(NN + TB - 1) / TB, TB>>>((const unsigned int*)ei);
    k_convert_count<<<(EE + TB - 1) / TB, TB>>>(ei);

    int conv_total = XCHUNKS + 2 * WCHUNKS;
    k_xwconv<<<(conv_total + TB - 1) / TB, TB>>>(x, Wl, Wr);

    // 4th launch -> ncu capture window
    dim3 ggrid((NN + 127) / 128, PP);
    k_gemm<<<ggrid, 256, GEMM_SMEM>>>(bl, br, att);

    k_scan1<<<SCAN_NB, SCAN_T>>>();
    k_scan23<<<SCAN_NB, SCAN_T>>>();
    k_scatter<<<(EE + TB - 1) / TB, TB>>>();

    int node_blocks = (NN * 32 + TB - 1) / TB;
    k_node_ln<<<node_blocks, TB>>>(att, out_bias, gamma, beta, out);
}

// round 13
// speedup vs baseline: 1.3895x; 1.3895x over previous
#include <cuda_runtime.h>
#include <cuda_fp16.h>
#include <math.h>

#define NN   50000
#define EE   800000
#define IND  128
#define OUTD 128
#define HH   4
#define CC   32
#define PP   3
#define TOT  384
#define NEGS 0.2f
#define LN_EPS 1e-5f

// ---------------- scratch (static device globals; no allocation) ------------
__device__ __half g_XLh[PP * NN * OUTD];   // fp16 x@Wl+bl per path
__device__ __half g_XRh[PP * NN * OUTD];   // fp16 x@Wr+br per path
__device__ __half g_xh[NN * IND];          // fp16 copy of x
__device__ __half g_Wlh[PP * IND * OUTD];  // fp16 Wl
__device__ __half g_Wrh[PP * IND * OUTD];  // fp16 Wr
__device__ float  g_ALs[PP * NN * HH];     // att-dot of xl per node/head
__device__ int    g_deg[NN];
__device__ int    g_off[NN];
__device__ int    g_wp[NN];
__device__ int    g_csr[EE];
__device__ int    g_bsum[64];
__device__ int    g_is64;

// 8-lane head-group sum (butterfly; redux.f32 does not exist on sm_100)
__device__ __forceinline__ float group8_sum(float v) {
    v += __shfl_xor_sync(0xffffffffu, v, 1);
    v += __shfl_xor_sync(0xffffffffu, v, 2);
    v += __shfl_xor_sync(0xffffffffu, v, 4);
    return v;
}

// ---------------- init: zero degrees + dtype probe (block 0) ----------------
__global__ void k_init(const unsigned int* __restrict__ ei32) {
    int i = blockIdx.x * blockDim.x + threadIdx.x;
    if (i < NN) g_deg[i] = 0;
    if (blockIdx.x == 0) {
        __shared__ int bad;
        if (threadIdx.x == 0) bad = 0;
        __syncthreads();
        int local = 0;
        for (int j = threadIdx.x; j < 4096; j += blockDim.x) {
            if (ei32[2 * j + 1] != 0u) local = 1;
        }
        if (local) atomicAdd(&bad, 1);
        __syncthreads();
        if (threadIdx.x == 0) g_is64 = (bad == 0) ? 1 : 0;
    }
}

// count dst degrees, reading edge_index directly (no intermediates)
__global__ void k_count(const void* __restrict__ ei) {
    int e = blockIdx.x * blockDim.x + threadIdx.x;
    if (e >= EE) return;
    int dst;
    if (g_is64) dst = (int)((const long long*)ei)[EE + e];
    else        dst = ((const int*)ei)[EE + e];
    atomicAdd(&g_deg[dst], 1);
}

// ---------------- pre-convert x / Wl / Wr to fp16 ---------------------------
__device__ __forceinline__ uint4 pack8h(float4 v0, float4 v1) {
    __half2 h0 = __floats2half2_rn(v0.x, v0.y);
    __half2 h1 = __floats2half2_rn(v0.z, v0.w);
    __half2 h2 = __floats2half2_rn(v1.x, v1.y);
    __half2 h3 = __floats2half2_rn(v1.z, v1.w);
    uint4 u;
    u.x = *(unsigned*)&h0; u.y = *(unsigned*)&h1;
    u.z = *(unsigned*)&h2; u.w = *(unsigned*)&h3;
    return u;
}

#define XCHUNKS (NN * IND / 8)            // 800000
#define WCHUNKS (PP * IND * OUTD / 8)     // 6144

__global__ void k_xwconv(const float* __restrict__ x,
                         const float* __restrict__ Wl,
                         const float* __restrict__ Wr) {
    int t = blockIdx.x * blockDim.x + threadIdx.x;
    if (t < XCHUNKS) {
        const float* sp = x + (size_t)t * 8;
        *(uint4*)&g_xh[(size_t)t * 8] =
            pack8h(*(const float4*)sp, *(const float4*)(sp + 4));
    } else if (t < XCHUNKS + WCHUNKS) {
        int i = t - XCHUNKS;
        const float* sp = Wl + (size_t)i * 8;
        *(uint4*)&g_Wlh[(size_t)i * 8] =
            pack8h(*(const float4*)sp, *(const float4*)(sp + 4));
    } else if (t < XCHUNKS + 2 * WCHUNKS) {
        int i = t - XCHUNKS - WCHUNKS;
        const float* sp = Wr + (size_t)i * 8;
        *(uint4*)&g_Wrh[(size_t)i * 8] =
            pack8h(*(const float4*)sp, *(const float4*)(sp + 4));
    }
}

// ---------------- exclusive scan over degrees -------------------------------
#define SCAN_T 1024
#define SCAN_NB ((NN + SCAN_T - 1) / SCAN_T)   // 49

__global__ void k_scan1() {
    __shared__ int sh[SCAN_T];
    int i = blockIdx.x * SCAN_T + threadIdx.x;
    int v = (i < NN) ? g_deg[i] : 0;
    sh[threadIdx.x] = v;
    __syncthreads();
    for (int d = 1; d < SCAN_T; d <<= 1) {
        int t = (threadIdx.x >= d) ? sh[threadIdx.x - d] : 0;
        __syncthreads();
        sh[threadIdx.x] += t;
        __syncthreads();
    }
    int incl = sh[threadIdx.x];
    if (i < NN) g_off[i] = incl - v;
    if (threadIdx.x == SCAN_T - 1) g_bsum[blockIdx.x] = incl;
}

__global__ void k_scan23() {
    __shared__ int pre;
    if (threadIdx.x == 0) {
        int r = 0;
        for (int b = 0; b < (int)blockIdx.x; b++) r += g_bsum[b];
        pre = r;
    }
    __syncthreads();
    int i = blockIdx.x * SCAN_T + threadIdx.x;
    if (i < NN) {
        int o = g_off[i] + pre;
        g_off[i] = o;
        g_wp[i]  = o;
    }
}

// scatter, reading edge_index directly
__global__ void k_scatter(const void* __restrict__ ei) {
    int e = blockIdx.x * blockDim.x + threadIdx.x;
    if (e >= EE) return;
    int src, dst;
    if (g_is64) {
        const long long* p = (const long long*)ei;
        src = (int)p[e];
        dst = (int)p[EE + e];
    } else {
        const int* p = (const int*)ei;
        src = p[e];
        dst = p[EE + e];
    }
    int pos = atomicAdd(&g_wp[dst], 1);
    g_csr[pos] = src;
}

// ---------------- fp16 tensor-core GEMM (m16n8k16 + ldmatrix) ---------------
// grid (391, 3). Whole-K fp16 tiles in smem; phases l/r. AL computed in
// phase-0 epilogue from register-resident accumulators (heads align to warps).
#define ST 136
#define A_OFF  0
#define BL_OFF (128 * ST)
#define BR_OFF (256 * ST)
#define GEMM_SMEM (384 * ST * 2)    // 104448 bytes

__global__ void __launch_bounds__(256) k_gemm(
    const float* __restrict__ bl, const float* __restrict__ br,
    const float* __restrict__ att) {
    extern __shared__ __half sm[];
    const int p    = blockIdx.y;
    const int tid  = threadIdx.x;
    const int wid  = tid >> 5;
    const int lane = tid & 31;
    const int wm   = wid & 3;
    const int wn   = wid >> 2;
    const int grp  = lane >> 2;
    const int tig  = lane & 3;
    const int sel  = lane >> 3;
    const int rin  = lane & 7;
    const int row0 = blockIdx.x * 128;

    for (int i = tid; i < 128 * 16; i += 256) {
        int r = i >> 4, seg = i & 15;
        uint4 v = make_uint4(0u, 0u, 0u, 0u);
        if (row0 + r < NN)
            v = *(const uint4*)&g_xh[(size_t)(row0 + r) * IND + seg * 8];
        *(uint4*)&sm[A_OFF + r * ST + seg * 8] = v;
    }
    for (int i = tid; i < 128 * 16; i += 256) {
        int k = i >> 4, seg = i & 15;
        *(uint4*)&sm[BL_OFF + k * ST + seg * 8] =
            *(const uint4*)&g_Wlh[((size_t)p * IND + k) * OUTD + seg * 8];
        *(uint4*)&sm[BR_OFF + k * ST + seg * 8] =
            *(const uint4*)&g_Wrh[((size_t)p * IND + k) * OUTD + seg * 8];
    }
    __syncthreads();

    const unsigned smem_u32 = (unsigned)__cvta_generic_to_shared(sm);

#pragma unroll
    for (int phase = 0; phase < 2; phase++) {
        const int boff = phase ? BR_OFF : BL_OFF;
        const float* bias = phase ? (br + p * OUTD) : (bl + p * OUTD);
        __half* out = phase ? (g_XRh + (size_t)p * NN * OUTD)
                            : (g_XLh + (size_t)p * NN * OUTD);

        float c[2][8][4];
#pragma unroll
        for (int mt = 0; mt < 2; mt++)
#pragma unroll
            for (int nt = 0; nt < 8; nt++)
#pragma unroll
                for (int j = 0; j < 4; j++) c[mt][nt][j] = 0.f;

#pragma unroll
        for (int ks = 0; ks < 8; ks++) {
            unsigned a[2][4];
#pragma unroll
            for (int mt = 0; mt < 2; mt++) {
                int arow = wm * 32 + mt * 16 + (sel & 1) * 8 + rin;
                int koff = ks * 16 + (sel >> 1) * 8;
                unsigned addr = smem_u32 + (unsigned)(A_OFF + arow * ST + koff) * 2u;
                asm volatile(
                    "ldmatrix.sync.aligned.m8n8.x4.shared.b16 {%0,%1,%2,%3}, [%4];"
                    : "=r"(a[mt][0]), "=r"(a[mt][1]), "=r"(a[mt][2]), "=r"(a[mt][3])
                    : "r"(addr));
            }
            unsigned b[4][4];
#pragma unroll
            for (int ntp = 0; ntp < 4; ntp++) {
                int n0   = wn * 64 + ntp * 16 + (sel >> 1) * 8;
                int krow = ks * 16 + (sel & 1) * 8 + rin;
                unsigned addr = smem_u32 + (unsigned)(boff + krow * ST + n0) * 2u;
                asm volatile(
                    "ldmatrix.sync.aligned.m8n8.x4.trans.shared.b16 {%0,%1,%2,%3}, [%4];"
                    : "=r"(b[ntp][0]), "=r"(b[ntp][1]), "=r"(b[ntp][2]), "=r"(b[ntp][3])
                    : "r"(addr));
            }
#pragma unroll
            for (int ntp = 0; ntp < 4; ntp++) {
#pragma unroll
                for (int half_n = 0; half_n < 2; half_n++) {
                    int nt = ntp * 2 + half_n;
                    unsigned b0 = b[ntp][half_n * 2];
                    unsigned b1 = b[ntp][half_n * 2 + 1];
#pragma unroll
                    for (int mt = 0; mt < 2; mt++) {
                        asm volatile(
                            "mma.sync.aligned.m16n8k16.row.col.f32.f16.f16.f32 "
                            "{%0,%1,%2,%3}, {%4,%5,%6,%7}, {%8,%9}, {%0,%1,%2,%3};"
                            : "+f"(c[mt][nt][0]), "+f"(c[mt][nt][1]),
                              "+f"(c[mt][nt][2]), "+f"(c[mt][nt][3])
                            : "r"(a[mt][0]), "r"(a[mt][1]),
                              "r"(a[mt][2]), "r"(a[mt][3]),
                              "r"(b0), "r"(b1));
                    }
                }
            }
        }

        // epilogue: +bias, fp16 store; phase 0 also reduces AL in-warp.
        float alp[4][2];
#pragma unroll
        for (int ri = 0; ri < 4; ri++) { alp[ri][0] = 0.f; alp[ri][1] = 0.f; }

#pragma unroll
        for (int mt = 0; mt < 2; mt++) {
#pragma unroll
            for (int nt = 0; nt < 8; nt++) {
                int col = wn * 64 + nt * 8 + 2 * tig;
                float b0 = bias[col], b1 = bias[col + 1];
                float v0 = c[mt][nt][0] + b0, v1 = c[mt][nt][1] + b1;
                float v2 = c[mt][nt][2] + b0, v3 = c[mt][nt][3] + b1;
                int r0 = row0 + wm * 32 + mt * 16 + grp;
                if (r0 < NN)
                    *(__half2*)(out + (size_t)r0 * OUTD + col) =
                        __floats2half2_rn(v0, v1);
                if (r0 + 8 < NN)
                    *(__half2*)(out + (size_t)(r0 + 8) * OUTD + col) =
                        __floats2half2_rn(v2, v3);
                if (phase == 0) {
                    float a0 = att[p * (HH * CC) + col];
                    float a1 = att[p * (HH * CC) + col + 1];
                    int h = nt >> 2;
                    alp[mt * 2 + 0][h] += a0 * v0 + a1 * v1;
                    alp[mt * 2 + 1][h] += a0 * v2 + a1 * v3;
                }
            }
        }
        if (phase == 0) {
#pragma unroll
            for (int ri = 0; ri < 4; ri++)
#pragma unroll
                for (int h = 0; h < 2; h++) {
                    alp[ri][h] += __shfl_xor_sync(0xffffffffu, alp[ri][h], 1);
                    alp[ri][h] += __shfl_xor_sync(0xffffffffu, alp[ri][h], 2);
                }
            if (tig == 0) {
#pragma unroll
                for (int ri = 0; ri < 4; ri++) {
                    int row = row0 + wm * 32 + (ri >> 1) * 16 + grp + (ri & 1) * 8;
                    if (row < NN) {
                        g_ALs[((size_t)p * NN + row) * HH + 2 * wn + 0] = alp[ri][0];
                        g_ALs[((size_t)p * NN + row) * HH + 2 * wn + 1] = alp[ri][1];
                    }
                }
            }
        }
    }
}

// ---------------- helpers ---------------------------------------------------
__device__ __forceinline__ float4 loadh4(const __half* base) {
    uint2 u = *(const uint2*)base;
    __half2 h0 = *(__half2*)&u.x;
    __half2 h1 = *(__half2*)&u.y;
    float2 f0 = __half22float2(h0);
    float2 f1 = __half22float2(h1);
    return make_float4(f0.x, f0.y, f1.x, f1.y);
}

// ---------------- fused node kernel: GATv2 (3 paths) + LayerNorm ------------
// R10 shape: interleaved paths (3 gathers in flight), single-edge prefetch,
// launch_bounds(256,3). score = 0.6*(AL[src]+AR[n]) + 0.4*sum att*|xl+xr|.
__global__ void __launch_bounds__(256, 3) k_node_ln(
    const float* __restrict__ att, const float* __restrict__ out_bias,
    const float* __restrict__ gamma, const float* __restrict__ beta,
    float* __restrict__ out) {
    int warp = (blockIdx.x * blockDim.x + threadIdx.x) >> 5;
    int lane = threadIdx.x & 31;
    if (warp >= NN) return;
    const int n = warp;
    const int hh = lane >> 3;

    const __half* XLbase[PP];
    const float*  ALbase[PP];
    float4 q[PP], a4[PP], acc[PP];
    float s[PP], base[PP];
#pragma unroll
    for (int p = 0; p < PP; p++) {
        XLbase[p] = g_XLh + (size_t)p * NN * OUTD + lane * 4;
        ALbase[p] = g_ALs + (size_t)p * NN * HH + hh;
        q[p]  = loadh4(g_XRh + ((size_t)p * NN + n) * OUTD + lane * 4);
        a4[p] = *(const float4*)(att + p * (HH * CC) + lane * 4);
        acc[p] = make_float4(0.f, 0.f, 0.f, 0.f);
        s[p] = 0.f;
        float t = a4[p].x * q[p].x + a4[p].y * q[p].y
                + a4[p].z * q[p].z + a4[p].w * q[p].w;
        base[p] = 0.6f * group8_sum(t);
    }

    const int off = g_off[n];
    const int deg = g_deg[n];

    auto edge = [&](const float4* xl, const float* al) {
#pragma unroll
        for (int p = 0; p < PP; p++) {
            float mx = xl[p].x + q[p].x, my = xl[p].y + q[p].y;
            float mz = xl[p].z + q[p].z, mw = xl[p].w + q[p].w;
            float t = a4[p].x * fabsf(mx) + a4[p].y * fabsf(my)
                    + a4[p].z * fabsf(mz) + a4[p].w * fabsf(mw);
            t = group8_sum(t);
            float score = fmaf(0.4f, t, fmaf(0.6f, al[p], base[p]));
            float pe = __expf(score);
            s[p] += pe;
            acc[p].x = fmaf(pe, xl[p].x, acc[p].x);
            acc[p].y = fmaf(pe, xl[p].y, acc[p].y);
            acc[p].z = fmaf(pe, xl[p].z, acc[p].z);
            acc[p].w = fmaf(pe, xl[p].w, acc[p].w);
        }
    };

    // self loop
    {
        float4 xl[PP]; float al[PP];
#pragma unroll
        for (int p = 0; p < PP; p++) {
            xl[p] = loadh4(XLbase[p] + (size_t)n * OUTD);
            al[p] = ALbase[p][(size_t)n * HH];
        }
        edge(xl, al);
    }
    // single-edge loop with next-index prefetch
    int nx = (deg > 0) ? g_csr[off] : 0;
    for (int e = 0; e < deg; e++) {
        int src = nx;
        if (e + 1 < deg) nx = g_csr[off + e + 1];
        float4 xl[PP]; float al[PP];
#pragma unroll
        for (int p = 0; p < PP; p++) {
            xl[p] = loadh4(XLbase[p] + (size_t)src * OUTD);
            al[p] = ALbase[p][(size_t)src * HH];
        }
        edge(xl, al);
    }

    // per-path epilogue: normalize, +out_bias, relu
    float4 o[PP];
    float sum = 0.f;
#pragma unroll
    for (int p = 0; p < PP; p++) {
        float inv = 1.f / s[p];
        const float* ob = out_bias + p * OUTD + lane * 4;
        o[p].x = fmaxf(0.f, acc[p].x * inv + ob[0]);
        o[p].y = fmaxf(0.f, acc[p].y * inv + ob[1]);
        o[p].z = fmaxf(0.f, acc[p].z * inv + ob[2]);
        o[p].w = fmaxf(0.f, acc[p].w * inv + ob[3]);
        sum += o[p].x + o[p].y + o[p].z + o[p].w;
    }

    // LayerNorm across 384 channels
#pragma unroll
    for (int d = 16; d >= 1; d >>= 1) sum += __shfl_xor_sync(0xffffffffu, sum, d);
    float mu = sum * (1.f / TOT);

    float vs = 0.f;
#pragma unroll
    for (int p = 0; p < PP; p++) {
        float dx = o[p].x - mu, dy = o[p].y - mu;
        float dz = o[p].z - mu, dw = o[p].w - mu;
        vs += dx * dx + dy * dy + dz * dz + dw * dw;
    }
#pragma unroll
    for (int d = 16; d >= 1; d >>= 1) vs += __shfl_xor_sync(0xffffffffu, vs, d);
    float r = rsqrtf(vs * (1.f / TOT) + LN_EPS);

#pragma unroll
    for (int p = 0; p < PP; p++) {
        int idx = p * OUTD + lane * 4;
        float4 g = *(const float4*)(gamma + idx);
        float4 b = *(const float4*)(beta + idx);
        float4 w;
        w.x = (o[p].x - mu) * r * g.x + b.x;
        w.y = (o[p].y - mu) * r * g.y + b.y;
        w.z = (o[p].z - mu) * r * g.z + b.z;
        w.w = (o[p].w - mu) * r * g.w + b.w;
        *(float4*)(out + (size_t)n * TOT + idx) = w;
    }
}

// ---------------- launch: fork GEMM branch parallel to CSR-build branch -----
extern "C" void kernel_launch(void* const* d_in, const int* in_sizes, int n_in,
                              void* d_out, int out_size) {
    const float* x        = (const float*)d_in[0];
    const void*  ei       = d_in[1];
    const float* Wl       = (const float*)d_in[2];
    const float* bl       = (const float*)d_in[3];
    const float* Wr       = (const float*)d_in[4];
    const float* br       = (const float*)d_in[5];
    const float* att      = (const float*)d_in[6];
    const float* out_bias = (const float*)d_in[7];
    const float* gamma    = (const float*)d_in[8];
    const float* beta     = (const float*)d_in[9];
    float* out = (float*)d_out;

    const int TB = 256;

    cudaFuncSetAttribute(k_gemm, cudaFuncAttributeMaxDynamicSharedMemorySize,
                         GEMM_SMEM);

    // fork/join objects (host-side; created per call, leaked — no device mem)
    cudaStream_t s2;
    cudaStreamCreateWithFlags(&s2, cudaStreamNonBlocking);
    cudaEvent_t evFork, evJoin;
    cudaEventCreateWithFlags(&evFork, cudaEventDisableTiming);
    cudaEventCreateWithFlags(&evJoin, cudaEventDisableTiming);

    // fork: side stream joins capture via event
    cudaEventRecord(evFork, 0);
    cudaStreamWaitEvent(s2, evFork, 0);

    // side branch: fp16 convert + GEMM (~72us)
    {
        int conv_total = XCHUNKS + 2 * WCHUNKS;
        k_xwconv<<<(conv_total + TB - 1) / TB, TB, 0, s2>>>(x, Wl, Wr);
        dim3 ggrid((NN + 127) / 128, PP);
        k_gemm<<<ggrid, 256, GEMM_SMEM, s2>>>(bl, br, att);
        cudaEventRecord(evJoin, s2);
    }

    // main branch: CSR build (~28us, hidden under the GEMM branch)
    k_init<<<(NN + TB - 1) / TB, TB>>>((const unsigned int*)ei);
    k_count<<<(EE + TB - 1) / TB, TB>>>(ei);
    k_scan1<<<SCAN_NB, SCAN_T>>>();
    k_scan23<<<SCAN_NB, SCAN_T>>>();
    k_scatter<<<(EE + TB - 1) / TB, TB>>>(ei);

    // join, then fused node+LN
    cudaStreamWaitEvent(0, evJoin, 0);
    int node_blocks = (NN * 32 + TB - 1) / TB;
    k_node_ln<<<node_blocks, TB>>>(att, out_bias, gamma, beta, out);
}